// round 1
// baseline (speedup 1.0000x reference)
#include <cuda_runtime.h>
#include <cstdint>

// Problem constants (fixed shapes per reference)
#define T_TOK   4096      // B*L
#define D_DIM   2048
#define E_NUM   8
#define DG      256
#define TOPK    2

// GEMM tile
#define BM 64
#define BN 128
#define KC 16
#define AS_STRIDE 68      // padded row stride for As (floats)

// ---------------- scratch (static device globals; no allocs) ----------------
__device__ int2   g_choice[T_TOK];
__device__ float2 g_gates[T_TOK];
__device__ int    g_list[E_NUM * T_TOK];    // tok2 = token*2 + slot
__device__ float  g_gatel[E_NUM * T_TOK];
__device__ int    g_cnt[E_NUM];
__device__ float  g_down_s[2 * T_TOK * DG];        // [tok2][DG]   8 MB
__device__ float  g_down[T_TOK * DG];              // [t][DG]      4 MB
__device__ float  g_up_s[(size_t)2 * T_TOK * D_DIM]; // [tok2][D]  64 MB

// ---------------- helpers ----------------
__device__ __forceinline__ void fma2(unsigned long long& d,
                                     unsigned long long a,
                                     unsigned long long b) {
    asm("fma.rn.f32x2 %0, %1, %2, %0;" : "+l"(d) : "l"(a), "l"(b));
}
__device__ __forceinline__ float f2lo(unsigned long long v) {
    return __uint_as_float((unsigned)(v & 0xffffffffull));
}
__device__ __forceinline__ float f2hi(unsigned long long v) {
    return __uint_as_float((unsigned)(v >> 32));
}

// ---------------- 1) gating: sigmoid(x @ Wg^T), top-2 ----------------
__global__ void __launch_bounds__(256) gate_kernel(const float* __restrict__ x,
                                                   const float* __restrict__ Wg) {
    int t = blockIdx.x;
    int w = threadIdx.x >> 5;       // warp = expert
    int lane = threadIdx.x & 31;
    const float4* xr = (const float4*)(x + (size_t)t * D_DIM);
    const float4* wr = (const float4*)(Wg + (size_t)w * D_DIM);
    float p = 0.f;
    #pragma unroll 4
    for (int i = lane; i < D_DIM / 4; i += 32) {
        float4 a = xr[i], b = wr[i];
        p += a.x * b.x + a.y * b.y + a.z * b.z + a.w * b.w;
    }
    #pragma unroll
    for (int o = 16; o; o >>= 1) p += __shfl_down_sync(0xffffffffu, p, o);
    __shared__ float s[E_NUM];
    if (lane == 0) s[w] = p;
    __syncthreads();
    if (threadIdx.x == 0) {
        float sv[E_NUM];
        #pragma unroll
        for (int e = 0; e < E_NUM; e++) sv[e] = 1.f / (1.f + expf(-s[e]));
        int i0 = 0; float b0 = sv[0];
        #pragma unroll
        for (int e = 1; e < E_NUM; e++) if (sv[e] > b0) { b0 = sv[e]; i0 = e; }
        int i1 = -1; float b1 = -1.f;
        #pragma unroll
        for (int e = 0; e < E_NUM; e++)
            if (e != i0 && sv[e] > b1) { b1 = sv[e]; i1 = e; }
        g_choice[t] = make_int2(i0, i1);
        g_gates[t]  = make_float2(b0, b1);
    }
}

// ---------------- 2) deterministic per-expert compaction ----------------
__global__ void __launch_bounds__(256) build_lists() {
    int e = blockIdx.x;
    int tid = threadIdx.x;
    int wid = tid >> 5, lane = tid & 31;
    __shared__ int sbase;
    __shared__ int wtot[8];
    if (tid == 0) sbase = 0;
    __syncthreads();
    for (int t0 = 0; t0 < T_TOK; t0 += 256) {
        int t = t0 + tid;
        int2 ch = g_choice[t];
        float2 gt = g_gates[t];
        int slot = -1; float g = 0.f;
        if (ch.x == e) { slot = 0; g = gt.x; }
        else if (ch.y == e) { slot = 1; g = gt.y; }
        bool flag = (slot >= 0);
        unsigned bal = __ballot_sync(0xffffffffu, flag);
        int wp = __popc(bal & ((1u << lane) - 1u));
        if (lane == 0) wtot[wid] = __popc(bal);
        __syncthreads();
        int off = 0;
        for (int i = 0; i < wid; i++) off += wtot[i];
        int tot = 0;
        for (int i = 0; i < 8; i++) tot += wtot[i];
        int base = sbase;
        if (flag) {
            int pos = base + off + wp;
            g_list[e * T_TOK + pos]  = t * 2 + slot;
            g_gatel[e * T_TOK + pos] = g;
        }
        __syncthreads();
        if (tid == 0) sbase = base + tot;
        __syncthreads();
    }
    if (tid == 0) g_cnt[e] = sbase;
}

// ---------------- 3/5) grouped GEMM (gathered A, per-expert B) ----------------
// C[tok2][nbase+n] = gate * sum_k A[token][k] * B[e][n][k]
__global__ void __launch_bounds__(256) moe_gemm(const float* __restrict__ A, int lda,
                                                const float* __restrict__ Bw,
                                                int K, int Nfull,
                                                float* __restrict__ outS) {
    int e = blockIdx.z;
    int cnt = g_cnt[e];
    int m0 = blockIdx.x * BM;
    if (m0 >= cnt) return;
    int nbase = blockIdx.y * BN;
    const float* Be = Bw + (size_t)e * Nfull * K;

    __shared__ float  As[KC * AS_STRIDE];
    __shared__ float2 Bs[KC * BN];
    __shared__ int    stok[BM];
    __shared__ float  sgate[BM];

    int tid = threadIdx.x;
    if (tid < BM) {
        int r = m0 + tid;
        if (r < cnt) { stok[tid] = g_list[e * T_TOK + r]; sgate[tid] = g_gatel[e * T_TOK + r]; }
        else         { stok[tid] = -1;                    sgate[tid] = 0.f; }
    }
    __syncthreads();

    int tx = tid & 31;      // 32 threads over N (4 each)
    int ty = tid >> 5;      // 8 threads over M (8 each)

    // A staging: thread -> (m = tid/4, kq = tid%4), loads one float4 per chunk
    int am  = tid >> 2;
    int akq = tid & 3;
    int atok = stok[am];
    const float4* Arow = (const float4*)(A + (size_t)(atok >= 0 ? (atok >> 1) : 0) * lda);

    // B staging: thread -> (n = tid/2, kh = tid%2), loads two float4 per chunk
    int bn  = tid >> 1;
    int bkh = tid & 1;
    const float* Brow = Be + (size_t)(nbase + bn) * K + bkh * 8;

    unsigned long long acc[4][4];
    #pragma unroll
    for (int i = 0; i < 4; i++)
        #pragma unroll
        for (int j = 0; j < 4; j++) acc[i][j] = 0ull;

    for (int k0 = 0; k0 < K; k0 += KC) {
        float4 av = Arow[(k0 >> 2) + akq];
        if (atok < 0) av = make_float4(0.f, 0.f, 0.f, 0.f);
        float4 bv0 = *(const float4*)(Brow + k0);
        float4 bv1 = *(const float4*)(Brow + k0 + 4);

        __syncthreads();
        {
            int kb = akq * 4;
            As[(kb + 0) * AS_STRIDE + am] = av.x;
            As[(kb + 1) * AS_STRIDE + am] = av.y;
            As[(kb + 2) * AS_STRIDE + am] = av.z;
            As[(kb + 3) * AS_STRIDE + am] = av.w;
        }
        {
            int kb = bkh * 8;
            Bs[(kb + 0) * BN + bn] = make_float2(bv0.x, bv0.x);
            Bs[(kb + 1) * BN + bn] = make_float2(bv0.y, bv0.y);
            Bs[(kb + 2) * BN + bn] = make_float2(bv0.z, bv0.z);
            Bs[(kb + 3) * BN + bn] = make_float2(bv0.w, bv0.w);
            Bs[(kb + 4) * BN + bn] = make_float2(bv1.x, bv1.x);
            Bs[(kb + 5) * BN + bn] = make_float2(bv1.y, bv1.y);
            Bs[(kb + 6) * BN + bn] = make_float2(bv1.z, bv1.z);
            Bs[(kb + 7) * BN + bn] = make_float2(bv1.w, bv1.w);
        }
        __syncthreads();

        #pragma unroll
        for (int kk = 0; kk < KC; kk++) {
            const unsigned long long* pa =
                (const unsigned long long*)(As + kk * AS_STRIDE + (ty << 3));
            const unsigned long long* pb =
                (const unsigned long long*)Bs + kk * BN + (tx << 2);
            unsigned long long a0 = pa[0], a1 = pa[1], a2 = pa[2], a3 = pa[3];
            unsigned long long b0 = pb[0], b1 = pb[1], b2 = pb[2], b3 = pb[3];
            fma2(acc[0][0], a0, b0); fma2(acc[0][1], a0, b1);
            fma2(acc[0][2], a0, b2); fma2(acc[0][3], a0, b3);
            fma2(acc[1][0], a1, b0); fma2(acc[1][1], a1, b1);
            fma2(acc[1][2], a1, b2); fma2(acc[1][3], a1, b3);
            fma2(acc[2][0], a2, b0); fma2(acc[2][1], a2, b1);
            fma2(acc[2][2], a2, b2); fma2(acc[2][3], a2, b3);
            fma2(acc[3][0], a3, b0); fma2(acc[3][1], a3, b1);
            fma2(acc[3][2], a3, b2); fma2(acc[3][3], a3, b3);
        }
    }

    // epilogue: scale by gate, scatter to per-slot scratch (exclusive -> no atomics)
    #pragma unroll
    for (int i = 0; i < 4; i++) {
        #pragma unroll
        for (int h = 0; h < 2; h++) {
            int mloc = (ty << 3) + (i << 1) + h;
            int r = m0 + mloc;
            if (r >= cnt) continue;
            int tk2 = stok[mloc];
            float g = sgate[mloc];
            float4 v;
            if (h == 0) {
                v.x = g * f2lo(acc[i][0]); v.y = g * f2lo(acc[i][1]);
                v.z = g * f2lo(acc[i][2]); v.w = g * f2lo(acc[i][3]);
            } else {
                v.x = g * f2hi(acc[i][0]); v.y = g * f2hi(acc[i][1]);
                v.z = g * f2hi(acc[i][2]); v.w = g * f2hi(acc[i][3]);
            }
            *(float4*)(outS + (size_t)tk2 * Nfull + nbase + (tx << 2)) = v;
        }
    }
}

// ---------------- 4) combine down slots ----------------
__global__ void __launch_bounds__(256) combine_down() {
    int i = blockIdx.x * 256 + threadIdx.x;          // over T_TOK*DG = 1M
    int t = i >> 8, g = i & 255;
    g_down[i] = g_down_s[(size_t)t * 512 + g] + g_down_s[(size_t)t * 512 + 256 + g];
}

// ---------------- 6) combine up slots -> output ----------------
__global__ void __launch_bounds__(256) combine_up(float* __restrict__ out) {
    int i = blockIdx.x * 256 + threadIdx.x;          // over (T_TOK*D)/4 float4s
    int t = i >> 9;                                   // 512 float4 per row
    int d4 = i & 511;
    const float4* a = (const float4*)(g_up_s + (size_t)t * 2 * D_DIM) + d4;
    const float4* b = (const float4*)(g_up_s + (size_t)t * 2 * D_DIM + D_DIM) + d4;
    float4 va = *a, vb = *b;
    float4 v = make_float4(va.x + vb.x, va.y + vb.y, va.z + vb.z, va.w + vb.w);
    ((float4*)out)[i] = v;
}

// ---------------- launcher ----------------
extern "C" void kernel_launch(void* const* d_in, const int* in_sizes, int n_in,
                              void* d_out, int out_size) {
    const float* x  = (const float*)d_in[0];
    const float* Wg = (const float*)d_in[1];
    const float* Wd = (const float*)d_in[2];
    const float* Wu = (const float*)d_in[3];
    float* out = (float*)d_out;

    float *p_down_s, *p_down, *p_up_s;
    cudaGetSymbolAddress((void**)&p_down_s, g_down_s);
    cudaGetSymbolAddress((void**)&p_down,   g_down);
    cudaGetSymbolAddress((void**)&p_up_s,   g_up_s);

    gate_kernel<<<T_TOK, 256>>>(x, Wg);
    build_lists<<<E_NUM, 256>>>();

    // down: A = x [T,2048] gathered, B = Wd [E][256][2048], out -> g_down_s
    moe_gemm<<<dim3(T_TOK / BM, DG / BN, E_NUM), 256>>>(x, D_DIM, Wd, D_DIM, DG, p_down_s);
    combine_down<<<(T_TOK * DG) / 256, 256>>>();

    // up: A = g_down [T,256] gathered, B = Wu [E][2048][256], out -> g_up_s
    moe_gemm<<<dim3(T_TOK / BM, D_DIM / BN, E_NUM), 256>>>(p_down, DG, Wu, DG, D_DIM, p_up_s);
    combine_up<<<(T_TOK * D_DIM / 4) / 256, 256>>>(out);
}

// round 2
// speedup vs baseline: 1.3252x; 1.3252x over previous
#include <cuda_runtime.h>
#include <cstdint>

// Problem constants (fixed shapes per reference)
#define T_TOK   4096      // B*L
#define D_DIM   2048
#define E_NUM   8
#define DG      256

// GEMM tile
#define BM   128
#define BN   64
#define KCC  8
#define ASTR 132          // As row stride (floats) — kills staging conflicts
#define BSTR 66           // Bs row stride (float2)

// ---------------- scratch (static device globals; no allocs) ----------------
__device__ int2   g_choice[T_TOK];
__device__ float2 g_gates[T_TOK];
__device__ int    g_list[E_NUM * T_TOK];    // tok2 = token*2 + slot
__device__ float  g_gatel[E_NUM * T_TOK];
__device__ int    g_cnt[E_NUM];
__device__ float  g_down_s[2 * T_TOK * DG];          // [tok2][DG]   8 MB
__device__ float  g_down[T_TOK * DG];                // [t][DG]      4 MB
__device__ float  g_up_s[(size_t)2 * T_TOK * D_DIM]; // [tok2][D]   64 MB

// ---------------- helpers ----------------
__device__ __forceinline__ void fma2(unsigned long long& d,
                                     unsigned long long a,
                                     unsigned long long b) {
    asm("fma.rn.f32x2 %0, %1, %2, %0;" : "+l"(d) : "l"(a), "l"(b));
}
__device__ __forceinline__ float f2lo(unsigned long long v) {
    return __uint_as_float((unsigned)(v & 0xffffffffull));
}
__device__ __forceinline__ float f2hi(unsigned long long v) {
    return __uint_as_float((unsigned)(v >> 32));
}

// ---------------- 1) gating: sigmoid(x @ Wg^T), top-2 ----------------
__global__ void __launch_bounds__(256) gate_kernel(const float* __restrict__ x,
                                                   const float* __restrict__ Wg) {
    int t = blockIdx.x;
    int w = threadIdx.x >> 5;       // warp = expert
    int lane = threadIdx.x & 31;
    const float4* xr = (const float4*)(x + (size_t)t * D_DIM);
    const float4* wr = (const float4*)(Wg + (size_t)w * D_DIM);
    float p = 0.f;
    #pragma unroll 4
    for (int i = lane; i < D_DIM / 4; i += 32) {
        float4 a = xr[i], b = wr[i];
        p += a.x * b.x + a.y * b.y + a.z * b.z + a.w * b.w;
    }
    #pragma unroll
    for (int o = 16; o; o >>= 1) p += __shfl_down_sync(0xffffffffu, p, o);
    __shared__ float s[E_NUM];
    if (lane == 0) s[w] = p;
    __syncthreads();
    if (threadIdx.x == 0) {
        float sv[E_NUM];
        #pragma unroll
        for (int e = 0; e < E_NUM; e++) sv[e] = 1.f / (1.f + expf(-s[e]));
        int i0 = 0; float b0 = sv[0];
        #pragma unroll
        for (int e = 1; e < E_NUM; e++) if (sv[e] > b0) { b0 = sv[e]; i0 = e; }
        int i1 = -1; float b1 = -1.f;
        #pragma unroll
        for (int e = 0; e < E_NUM; e++)
            if (e != i0 && sv[e] > b1) { b1 = sv[e]; i1 = e; }
        g_choice[t] = make_int2(i0, i1);
        g_gates[t]  = make_float2(b0, b1);
    }
}

// ---------------- 2) deterministic per-expert compaction ----------------
__global__ void __launch_bounds__(256) build_lists() {
    int e = blockIdx.x;
    int tid = threadIdx.x;
    int wid = tid >> 5, lane = tid & 31;
    __shared__ int sbase;
    __shared__ int wtot[8];
    if (tid == 0) sbase = 0;
    __syncthreads();
    for (int t0 = 0; t0 < T_TOK; t0 += 256) {
        int t = t0 + tid;
        int2 ch = g_choice[t];
        float2 gt = g_gates[t];
        int slot = -1; float g = 0.f;
        if (ch.x == e) { slot = 0; g = gt.x; }
        else if (ch.y == e) { slot = 1; g = gt.y; }
        bool flag = (slot >= 0);
        unsigned bal = __ballot_sync(0xffffffffu, flag);
        int wp = __popc(bal & ((1u << lane) - 1u));
        if (lane == 0) wtot[wid] = __popc(bal);
        __syncthreads();
        int off = 0;
        for (int i = 0; i < wid; i++) off += wtot[i];
        int tot = 0;
        for (int i = 0; i < 8; i++) tot += wtot[i];
        int base = sbase;
        if (flag) {
            int pos = base + off + wp;
            g_list[e * T_TOK + pos]  = t * 2 + slot;
            g_gatel[e * T_TOK + pos] = g;
        }
        __syncthreads();
        if (tid == 0) sbase = base + tot;
        __syncthreads();
    }
    if (tid == 0) g_cnt[e] = sbase;
}

// ---------------- 3/5) grouped GEMM, f32x2, double-buffered ----------------
// C[tok2][nbase+n] = gate * sum_k A[token][k] * B[e][n][k]
// Per-thread tile 8m x 4n; FMA-pipe-bound inner loop:
//   4 LDS.64 (A pairs, warp-broadcast) + 4 LDS.64 (B dup pairs, conflict-free)
//   + 16 fma.rn.f32x2 per k.
__global__ void __launch_bounds__(256) moe_gemm(const float* __restrict__ A, int lda,
                                                const float* __restrict__ Bw,
                                                int K, int Nfull,
                                                float* __restrict__ outS) {
    int e = blockIdx.z;
    int cnt = g_cnt[e];
    int m0 = blockIdx.x * BM;
    if (m0 >= cnt) return;
    int nbase = blockIdx.y * BN;
    const float* Be = Bw + (size_t)e * Nfull * K;

    __shared__ __align__(16) float  As[2][KCC][ASTR];
    __shared__ __align__(16) float2 Bs[2][KCC][BSTR];
    __shared__ int    stok[BM];
    __shared__ float  sgate[BM];

    int tid = threadIdx.x;
    if (tid < BM) {
        int r = m0 + tid;
        if (r < cnt) { stok[tid] = g_list[e * T_TOK + r]; sgate[tid] = g_gatel[e * T_TOK + r]; }
        else         { stok[tid] = -1;                    sgate[tid] = 0.f; }
    }
    __syncthreads();

    // staging roles
    int am  = tid >> 1, akq = tid & 1;          // A: 128 m-rows x 2 k-quads
    int atok = stok[am];
    const float* Arow = A + (size_t)(atok >= 0 ? (atok >> 1) : 0) * lda + akq * 4;
    int bn  = (tid & 127) >> 1, bkq = tid & 1;  // B: 64 n-rows x 2 k-quads (tid<128)
    bool doB = tid < 128;
    const float* Brow = Be + (size_t)(nbase + bn) * K + bkq * 4;

    // prologue: chunk 0 -> buf 0
    float4 avr = *(const float4*)Arow;
    float4 bvr = make_float4(0.f, 0.f, 0.f, 0.f);
    if (doB) bvr = *(const float4*)Brow;
    {
        const float* af = (const float*)&avr;
        #pragma unroll
        for (int q = 0; q < 4; q++) As[0][akq * 4 + q][am] = af[q];
        if (doB) {
            const float* bf = (const float*)&bvr;
            #pragma unroll
            for (int q = 0; q < 4; q++)
                Bs[0][bkq * 4 + q][bn] = make_float2(bf[q], bf[q]);
        }
    }
    __syncthreads();

    int tx = tid & 15, ty = tid >> 4;   // 16x16 threads; thread tile 8m x 4n

    unsigned long long acc[4][4];
    #pragma unroll
    for (int i = 0; i < 4; i++)
        #pragma unroll
        for (int j = 0; j < 4; j++) acc[i][j] = 0ull;

    int C = K / KCC;
    for (int c = 0; c < C; c++) {
        int cur = c & 1;
        if (c + 1 < C) {                 // prefetch next chunk into registers
            avr = *(const float4*)(Arow + (c + 1) * KCC);
            if (doB) bvr = *(const float4*)(Brow + (c + 1) * KCC);
        }
        #pragma unroll
        for (int kk = 0; kk < KCC; kk++) {
            const unsigned long long* pa =
                (const unsigned long long*)&As[cur][kk][ty * 8];
            const unsigned long long* pb =
                (const unsigned long long*)&Bs[cur][kk][tx];
            unsigned long long a0 = pa[0], a1 = pa[1], a2 = pa[2], a3 = pa[3];
            unsigned long long b0 = pb[0],  b1 = pb[16],
                               b2 = pb[32], b3 = pb[48];
            fma2(acc[0][0], a0, b0); fma2(acc[0][1], a0, b1);
            fma2(acc[0][2], a0, b2); fma2(acc[0][3], a0, b3);
            fma2(acc[1][0], a1, b0); fma2(acc[1][1], a1, b1);
            fma2(acc[1][2], a1, b2); fma2(acc[1][3], a1, b3);
            fma2(acc[2][0], a2, b0); fma2(acc[2][1], a2, b1);
            fma2(acc[2][2], a2, b2); fma2(acc[2][3], a2, b3);
            fma2(acc[3][0], a3, b0); fma2(acc[3][1], a3, b1);
            fma2(acc[3][2], a3, b2); fma2(acc[3][3], a3, b3);
        }
        if (c + 1 < C) {                 // store next chunk -> other buffer
            int nb = 1 - cur;
            const float* af = (const float*)&avr;
            #pragma unroll
            for (int q = 0; q < 4; q++) As[nb][akq * 4 + q][am] = af[q];
            if (doB) {
                const float* bf = (const float*)&bvr;
                #pragma unroll
                for (int q = 0; q < 4; q++)
                    Bs[nb][bkq * 4 + q][bn] = make_float2(bf[q], bf[q]);
            }
            __syncthreads();             // single barrier per chunk
        }
    }

    // epilogue: gate-scale, scatter to exclusive (token,slot) scratch rows
    #pragma unroll
    for (int i = 0; i < 4; i++) {
        #pragma unroll
        for (int h = 0; h < 2; h++) {
            int mL = ty * 8 + 2 * i + h;
            if (m0 + mL >= cnt) continue;
            int tk2 = stok[mL];
            float g = sgate[mL];
            float* orow = outS + (size_t)tk2 * Nfull + nbase + tx;
            if (h == 0) {
                orow[0]  = g * f2lo(acc[i][0]);
                orow[16] = g * f2lo(acc[i][1]);
                orow[32] = g * f2lo(acc[i][2]);
                orow[48] = g * f2lo(acc[i][3]);
            } else {
                orow[0]  = g * f2hi(acc[i][0]);
                orow[16] = g * f2hi(acc[i][1]);
                orow[32] = g * f2hi(acc[i][2]);
                orow[48] = g * f2hi(acc[i][3]);
            }
        }
    }
}

// ---------------- 4) combine down slots ----------------
__global__ void __launch_bounds__(256) combine_down() {
    int i = blockIdx.x * 256 + threadIdx.x;          // over T_TOK*DG = 1M
    int t = i >> 8, g = i & 255;
    g_down[i] = g_down_s[(size_t)t * 512 + g] + g_down_s[(size_t)t * 512 + 256 + g];
}

// ---------------- 6) combine up slots -> output ----------------
__global__ void __launch_bounds__(256) combine_up(float* __restrict__ out) {
    int i = blockIdx.x * 256 + threadIdx.x;          // over (T_TOK*D)/4 float4s
    int t = i >> 9;                                   // 512 float4 per row
    int d4 = i & 511;
    const float4* a = (const float4*)(g_up_s + (size_t)t * 2 * D_DIM) + d4;
    const float4* b = (const float4*)(g_up_s + (size_t)t * 2 * D_DIM + D_DIM) + d4;
    float4 va = *a, vb = *b;
    float4 v = make_float4(va.x + vb.x, va.y + vb.y, va.z + vb.z, va.w + vb.w);
    ((float4*)out)[i] = v;
}

// ---------------- launcher ----------------
extern "C" void kernel_launch(void* const* d_in, const int* in_sizes, int n_in,
                              void* d_out, int out_size) {
    const float* x  = (const float*)d_in[0];
    const float* Wg = (const float*)d_in[1];
    const float* Wd = (const float*)d_in[2];
    const float* Wu = (const float*)d_in[3];
    float* out = (float*)d_out;

    float *p_down_s, *p_down, *p_up_s;
    cudaGetSymbolAddress((void**)&p_down_s, g_down_s);
    cudaGetSymbolAddress((void**)&p_down,   g_down);
    cudaGetSymbolAddress((void**)&p_up_s,   g_up_s);

    gate_kernel<<<T_TOK, 256>>>(x, Wg);
    build_lists<<<E_NUM, 256>>>();

    // down: A = x [T,2048] gathered, B = Wd [E][256][2048] -> g_down_s
    moe_gemm<<<dim3(T_TOK / BM, DG / BN, E_NUM), 256>>>(x, D_DIM, Wd, D_DIM, DG, p_down_s);
    combine_down<<<(T_TOK * DG) / 256, 256>>>();

    // up: A = g_down [T,256] gathered, B = Wu [E][2048][256] -> g_up_s
    moe_gemm<<<dim3(T_TOK / BM, D_DIM / BN, E_NUM), 256>>>(p_down, DG, Wu, DG, D_DIM, p_up_s);
    combine_up<<<(T_TOK * D_DIM / 4) / 256, 256>>>(out);
}

// round 4
// speedup vs baseline: 2.6120x; 1.9710x over previous
#include <cuda_runtime.h>
#include <cuda_bf16.h>
#include <cstdint>

#define T_TOK 4096
#define D_DIM 2048
#define E_NUM 8
#define DG    256

#define BM 128
#define BN 128
#define BK 16
#define STAGES 4
#define ROWB 48                       // smem bytes per row: 32B data + 16B pad
#define MATB (128 * ROWB)             // 6144 per matrix tile
#define STGB (4 * MATB)               // Ah,Al,Bh,Bl per stage = 24576
#define SMEM_DYN (STAGES * STGB)      // 98304

// ---------------- scratch (device globals; no runtime allocs) ----------------
__device__ uint16_t g_xh[(size_t)T_TOK * D_DIM];
__device__ uint16_t g_xl[(size_t)T_TOK * D_DIM];
__device__ uint16_t g_wdh[(size_t)E_NUM * DG * D_DIM];
__device__ uint16_t g_wdl[(size_t)E_NUM * DG * D_DIM];
__device__ uint16_t g_wuh[(size_t)E_NUM * D_DIM * DG];
__device__ uint16_t g_wul[(size_t)E_NUM * D_DIM * DG];
__device__ uint16_t g_dnh[(size_t)T_TOK * DG];
__device__ uint16_t g_dnl[(size_t)T_TOK * DG];
__device__ int2   g_choice[T_TOK];
__device__ float2 g_gates[T_TOK];
__device__ int    g_list[E_NUM * T_TOK];
__device__ float  g_gatel[E_NUM * T_TOK];
__device__ int    g_cnt[E_NUM];
__device__ float  g_down_s[2 * T_TOK * DG];            // [tok2][DG]
__device__ float  g_up_s[(size_t)2 * T_TOK * D_DIM];   // [tok2][D]

// ---------------- PTX helpers (all baseline sm_80/90 PTX) ----------------
__device__ __forceinline__ uint32_t smem_u32(const void* p) {
    uint32_t a;
    asm("{ .reg .u64 t; cvta.to.shared.u64 t, %1; cvt.u32.u64 %0, t; }" : "=r"(a) : "l"(p));
    return a;
}
__device__ __forceinline__ void cpa16(uint32_t s, const void* g) {
    asm volatile("cp.async.cg.shared.global [%0], [%1], 16;" :: "r"(s), "l"(g));
}
#define CP_COMMIT() asm volatile("cp.async.commit_group;" ::: "memory")
#define CP_WAIT2()  asm volatile("cp.async.wait_group 2;" ::: "memory")

__device__ __forceinline__ void ldsm4(uint32_t* r, uint32_t addr) {
    asm volatile("ldmatrix.sync.aligned.m8n8.x4.shared.b16 {%0,%1,%2,%3}, [%4];"
                 : "=r"(r[0]), "=r"(r[1]), "=r"(r[2]), "=r"(r[3]) : "r"(addr));
}
__device__ __forceinline__ void mma16816(float* c, const uint32_t* a,
                                         uint32_t b0, uint32_t b1) {
    asm volatile(
        "mma.sync.aligned.m16n8k16.row.col.f32.bf16.bf16.f32 "
        "{%0,%1,%2,%3}, {%4,%5,%6,%7}, {%8,%9}, {%0,%1,%2,%3};"
        : "+f"(c[0]), "+f"(c[1]), "+f"(c[2]), "+f"(c[3])
        : "r"(a[0]), "r"(a[1]), "r"(a[2]), "r"(a[3]), "r"(b0), "r"(b1));
}

// ---------------- 1) split conversion fp32 -> bf16 hi/lo ----------------
__device__ __forceinline__ uint16_t bfr(__nv_bfloat16 h) {
    return *reinterpret_cast<uint16_t*>(&h);
}
__global__ void __launch_bounds__(256) conv_split(const float4* __restrict__ src,
                                                  uint2* __restrict__ hi,
                                                  uint2* __restrict__ lo, int n4) {
    int i = blockIdx.x * 256 + threadIdx.x;
    if (i >= n4) return;
    float4 v = src[i];
    __nv_bfloat16 h0 = __float2bfloat16(v.x), h1 = __float2bfloat16(v.y),
                  h2 = __float2bfloat16(v.z), h3 = __float2bfloat16(v.w);
    __nv_bfloat16 l0 = __float2bfloat16(v.x - __bfloat162float(h0));
    __nv_bfloat16 l1 = __float2bfloat16(v.y - __bfloat162float(h1));
    __nv_bfloat16 l2 = __float2bfloat16(v.z - __bfloat162float(h2));
    __nv_bfloat16 l3 = __float2bfloat16(v.w - __bfloat162float(h3));
    uint2 H, L;
    H.x = (uint32_t)bfr(h0) | ((uint32_t)bfr(h1) << 16);
    H.y = (uint32_t)bfr(h2) | ((uint32_t)bfr(h3) << 16);
    L.x = (uint32_t)bfr(l0) | ((uint32_t)bfr(l1) << 16);
    L.y = (uint32_t)bfr(l2) | ((uint32_t)bfr(l3) << 16);
    hi[i] = H; lo[i] = L;
}

// ---------------- 2) gating ----------------
__global__ void __launch_bounds__(256) gate_kernel(const float* __restrict__ x,
                                                   const float* __restrict__ Wg) {
    int t = blockIdx.x;
    int w = threadIdx.x >> 5, lane = threadIdx.x & 31;
    const float4* xr = (const float4*)(x + (size_t)t * D_DIM);
    const float4* wr = (const float4*)(Wg + (size_t)w * D_DIM);
    float p = 0.f;
    #pragma unroll 4
    for (int i = lane; i < D_DIM / 4; i += 32) {
        float4 a = xr[i], b = wr[i];
        p += a.x * b.x + a.y * b.y + a.z * b.z + a.w * b.w;
    }
    #pragma unroll
    for (int o = 16; o; o >>= 1) p += __shfl_down_sync(0xffffffffu, p, o);
    __shared__ float s[E_NUM];
    if (lane == 0) s[w] = p;
    __syncthreads();
    if (threadIdx.x == 0) {
        float sv[E_NUM];
        #pragma unroll
        for (int e = 0; e < E_NUM; e++) sv[e] = 1.f / (1.f + expf(-s[e]));
        int i0 = 0; float b0 = sv[0];
        #pragma unroll
        for (int e = 1; e < E_NUM; e++) if (sv[e] > b0) { b0 = sv[e]; i0 = e; }
        int i1 = -1; float b1 = -1.f;
        #pragma unroll
        for (int e = 0; e < E_NUM; e++) if (e != i0 && sv[e] > b1) { b1 = sv[e]; i1 = e; }
        g_choice[t] = make_int2(i0, i1);
        g_gates[t]  = make_float2(b0, b1);
    }
}

// ---------------- 3) deterministic per-expert compaction ----------------
__global__ void __launch_bounds__(256) build_lists() {
    int e = blockIdx.x, tid = threadIdx.x;
    int wid = tid >> 5, lane = tid & 31;
    __shared__ int sbase;
    __shared__ int wtot[8];
    if (tid == 0) sbase = 0;
    __syncthreads();
    for (int t0 = 0; t0 < T_TOK; t0 += 256) {
        int t = t0 + tid;
        int2 ch = g_choice[t];
        float2 gt = g_gates[t];
        int slot = -1; float g = 0.f;
        if (ch.x == e) { slot = 0; g = gt.x; }
        else if (ch.y == e) { slot = 1; g = gt.y; }
        bool flag = (slot >= 0);
        unsigned bal = __ballot_sync(0xffffffffu, flag);
        int wp = __popc(bal & ((1u << lane) - 1u));
        if (lane == 0) wtot[wid] = __popc(bal);
        __syncthreads();
        int off = 0;
        for (int i = 0; i < wid; i++) off += wtot[i];
        int tot = 0;
        for (int i = 0; i < 8; i++) tot += wtot[i];
        int base = sbase;
        if (flag) {
            int pos = base + off + wp;
            g_list[e * T_TOK + pos]  = t * 2 + slot;
            g_gatel[e * T_TOK + pos] = g;
        }
        __syncthreads();
        if (tid == 0) sbase = base + tot;
        __syncthreads();
    }
    if (tid == 0) g_cnt[e] = sbase;
}

// ---------------- 4) grouped GEMM: mma.sync bf16 x3, cp.async 4-stage ----------
// C[tok2][nbase+n] = gate * sum_k A[tok][k] * B[e*Nfull+n][k]
__global__ void __launch_bounds__(256) moe_gemm_mma(
    const uint16_t* __restrict__ Ah, const uint16_t* __restrict__ Al, int lda,
    const uint16_t* __restrict__ Bh, const uint16_t* __restrict__ Bl,
    int K, int Nfull, float* __restrict__ outS) {
    extern __shared__ char smem[];
    __shared__ int   stok[BM];
    __shared__ float sgate[BM];

    int e = blockIdx.z;
    int cnt = g_cnt[e];
    int m0 = blockIdx.x * BM;
    if (m0 >= cnt) return;
    int nbase = blockIdx.y * BN;
    int tid = threadIdx.x;

    if (tid < BM) {
        int r = m0 + tid;
        if (r < cnt) { stok[tid] = g_list[e * T_TOK + r]; sgate[tid] = g_gatel[e * T_TOK + r]; }
        else         { stok[tid] = 0;                     sgate[tid] = 0.f; }
    }
    __syncthreads();

    // cp.async roles: thread -> (row = tid/2, 16B-half q = tid&1) for all 4 matrices
    int srow = tid >> 1, q = tid & 1;
    int tokrow = stok[srow] >> 1;
    const uint16_t* gAh = Ah + (size_t)tokrow * lda + q * 8;
    const uint16_t* gAl = Al + (size_t)tokrow * lda + q * 8;
    size_t bro = ((size_t)e * Nfull + nbase + srow) * K + q * 8;
    const uint16_t* gBh = Bh + bro;
    const uint16_t* gBl = Bl + bro;
    uint32_t smb = smem_u32(smem);
    uint32_t so = (uint32_t)srow * ROWB + (uint32_t)q * 16;

    int C = K / BK;
    // prologue: stages 0..STAGES-2
    #pragma unroll
    for (int s = 0; s < STAGES - 1; s++) {
        if (s < C) {
            uint32_t sb = smb + s * STGB;
            int k0 = s * BK;
            cpa16(sb + so,            gAh + k0);
            cpa16(sb + MATB + so,     gAl + k0);
            cpa16(sb + 2 * MATB + so, gBh + k0);
            cpa16(sb + 3 * MATB + so, gBl + k0);
        }
        CP_COMMIT();
    }

    int wid = tid >> 5, lane = tid & 31;
    int wm = (wid & 3) * 32;      // 4 warps along M
    int wn = (wid >> 2) * 64;     // 2 warps along N
    uint32_t lrow = (uint32_t)(lane & 15);
    uint32_t lkb  = (uint32_t)(lane >> 4) * 16;

    float acc[2][8][4];
    #pragma unroll
    for (int i = 0; i < 2; i++)
        #pragma unroll
        for (int j = 0; j < 8; j++)
            #pragma unroll
            for (int v = 0; v < 4; v++) acc[i][j][v] = 0.f;

    #pragma unroll 1
    for (int c = 0; c < C; c++) {
        CP_WAIT2();
        __syncthreads();
        uint32_t sb = smb + (uint32_t)(c & (STAGES - 1)) * STGB;

        uint32_t ah[2][4], al[2][4], bh[4][4], bl[4][4];
        #pragma unroll
        for (int i = 0; i < 2; i++) {
            uint32_t a = sb + (wm + i * 16 + lrow) * ROWB + lkb;
            ldsm4(ah[i], a);
            ldsm4(al[i], a + MATB);
        }
        #pragma unroll
        for (int gq = 0; gq < 4; gq++) {
            uint32_t a = sb + 2 * MATB + (wn + gq * 16 + lrow) * ROWB + lkb;
            ldsm4(bh[gq], a);
            ldsm4(bl[gq], a + MATB);
        }
        #pragma unroll
        for (int i = 0; i < 2; i++)
            #pragma unroll
            for (int j = 0; j < 8; j++) {
                int gq = j >> 1, o = j & 1;
                uint32_t b0h = bh[gq][o], b1h = bh[gq][o + 2];
                mma16816(acc[i][j], ah[i], b0h, b1h);
                mma16816(acc[i][j], ah[i], bl[gq][o], bl[gq][o + 2]);
                mma16816(acc[i][j], al[i], b0h, b1h);
            }

        int nc = c + STAGES - 1;
        if (nc < C) {
            uint32_t sb2 = smb + (uint32_t)(nc & (STAGES - 1)) * STGB;
            int k0 = nc * BK;
            cpa16(sb2 + so,            gAh + k0);
            cpa16(sb2 + MATB + so,     gAl + k0);
            cpa16(sb2 + 2 * MATB + so, gBh + k0);
            cpa16(sb2 + 3 * MATB + so, gBl + k0);
        }
        CP_COMMIT();
    }

    // epilogue: gate-scale, exclusive (token,slot) scatter; per row a dense
    // contiguous 64-col span is written (no wasted sectors).
    #pragma unroll
    for (int i = 0; i < 2; i++) {
        #pragma unroll
        for (int half = 0; half < 2; half++) {
            int mloc = wm + i * 16 + (lane >> 2) + half * 8;
            if (m0 + mloc >= cnt) continue;
            int tk2 = stok[mloc];
            float g = sgate[mloc];
            float* orow = outS + (size_t)tk2 * Nfull + nbase + wn + (lane & 3) * 2;
            #pragma unroll
            for (int j = 0; j < 8; j++) {
                float2 v;
                v.x = g * acc[i][j][half * 2 + 0];
                v.y = g * acc[i][j][half * 2 + 1];
                *(float2*)(orow + j * 8) = v;
            }
        }
    }
}

// ---------------- 5) combine down slots + split to bf16 hi/lo ----------------
__global__ void __launch_bounds__(256) combine_down_split() {
    int i = blockIdx.x * 256 + threadIdx.x;   // over T_TOK*DG/4
    int t = i >> 6, c4 = i & 63;
    const float4* s = (const float4*)g_down_s;
    float4 a = s[t * 128 + c4];
    float4 b = s[t * 128 + 64 + c4];
    float4 v = make_float4(a.x + b.x, a.y + b.y, a.z + b.z, a.w + b.w);
    __nv_bfloat16 h0 = __float2bfloat16(v.x), h1 = __float2bfloat16(v.y),
                  h2 = __float2bfloat16(v.z), h3 = __float2bfloat16(v.w);
    __nv_bfloat16 l0 = __float2bfloat16(v.x - __bfloat162float(h0));
    __nv_bfloat16 l1 = __float2bfloat16(v.y - __bfloat162float(h1));
    __nv_bfloat16 l2 = __float2bfloat16(v.z - __bfloat162float(h2));
    __nv_bfloat16 l3 = __float2bfloat16(v.w - __bfloat162float(h3));
    uint2 H, L;
    H.x = (uint32_t)bfr(h0) | ((uint32_t)bfr(h1) << 16);
    H.y = (uint32_t)bfr(h2) | ((uint32_t)bfr(h3) << 16);
    L.x = (uint32_t)bfr(l0) | ((uint32_t)bfr(l1) << 16);
    L.y = (uint32_t)bfr(l2) | ((uint32_t)bfr(l3) << 16);
    ((uint2*)g_dnh)[i] = H;
    ((uint2*)g_dnl)[i] = L;
}

// ---------------- 6) combine up slots -> output ----------------
__global__ void __launch_bounds__(256) combine_up(float* __restrict__ out) {
    int i = blockIdx.x * 256 + threadIdx.x;   // over (T_TOK*D)/4
    int t = i >> 9, d4 = i & 511;
    const float4* a = (const float4*)(g_up_s + (size_t)t * 2 * D_DIM) + d4;
    const float4* b = (const float4*)(g_up_s + (size_t)t * 2 * D_DIM + D_DIM) + d4;
    float4 va = *a, vb = *b;
    ((float4*)out)[i] = make_float4(va.x + vb.x, va.y + vb.y, va.z + vb.z, va.w + vb.w);
}

// ---------------- launcher ----------------
extern "C" void kernel_launch(void* const* d_in, const int* in_sizes, int n_in,
                              void* d_out, int out_size) {
    const float* x  = (const float*)d_in[0];
    const float* Wg = (const float*)d_in[1];
    const float* Wd = (const float*)d_in[2];
    const float* Wu = (const float*)d_in[3];
    float* out = (float*)d_out;

    cudaFuncSetAttribute(moe_gemm_mma, cudaFuncAttributeMaxDynamicSharedMemorySize, SMEM_DYN);

    void *p_xh, *p_xl, *p_wdh, *p_wdl, *p_wuh, *p_wul, *p_dnh, *p_dnl, *p_ds, *p_us;
    cudaGetSymbolAddress(&p_xh, g_xh);   cudaGetSymbolAddress(&p_xl, g_xl);
    cudaGetSymbolAddress(&p_wdh, g_wdh); cudaGetSymbolAddress(&p_wdl, g_wdl);
    cudaGetSymbolAddress(&p_wuh, g_wuh); cudaGetSymbolAddress(&p_wul, g_wul);
    cudaGetSymbolAddress(&p_dnh, g_dnh); cudaGetSymbolAddress(&p_dnl, g_dnl);
    cudaGetSymbolAddress(&p_ds, g_down_s); cudaGetSymbolAddress(&p_us, g_up_s);

    conv_split<<<(T_TOK * D_DIM / 4) / 256, 256>>>((const float4*)x, (uint2*)p_xh, (uint2*)p_xl, T_TOK * D_DIM / 4);
    conv_split<<<(E_NUM * DG * D_DIM / 4) / 256, 256>>>((const float4*)Wd, (uint2*)p_wdh, (uint2*)p_wdl, E_NUM * DG * D_DIM / 4);
    conv_split<<<(E_NUM * DG * D_DIM / 4) / 256, 256>>>((const float4*)Wu, (uint2*)p_wuh, (uint2*)p_wul, E_NUM * DG * D_DIM / 4);
    gate_kernel<<<T_TOK, 256>>>(x, Wg);
    build_lists<<<E_NUM, 256>>>();

    // down: A = split(x) gathered [T,2048], B = split(Wd) [E][256][2048]
    moe_gemm_mma<<<dim3(T_TOK / BM, DG / BN, E_NUM), 256, SMEM_DYN>>>(
        (const uint16_t*)p_xh, (const uint16_t*)p_xl, D_DIM,
        (const uint16_t*)p_wdh, (const uint16_t*)p_wdl, D_DIM, DG, (float*)p_ds);
    combine_down_split<<<(T_TOK * DG / 4) / 256, 256>>>();

    // up: A = split(down) gathered [T,256], B = split(Wu) [E][2048][256]
    moe_gemm_mma<<<dim3(T_TOK / BM, D_DIM / BN, E_NUM), 256, SMEM_DYN>>>(
        (const uint16_t*)p_dnh, (const uint16_t*)p_dnl, DG,
        (const uint16_t*)p_wuh, (const uint16_t*)p_wul, DG, D_DIM, (float*)p_us);
    combine_up<<<(T_TOK * D_DIM / 4) / 256, 256>>>(out);
}

// round 5
// speedup vs baseline: 2.8500x; 1.0911x over previous
#include <cuda_runtime.h>
#include <cuda_bf16.h>
#include <cstdint>

#define T_TOK 4096
#define D_DIM 2048
#define E_NUM 8
#define DG    256

#define BM 128
#define BK 16
#define STAGES 4
#define ROWB 48                       // smem bytes per row: 32B data + 16B pad
#define MATB (128 * ROWB)             // 6144 bytes per 128-row matrix tile

#define NX4  (T_TOK * D_DIM / 4)          // float4 count of x
#define NW4  (E_NUM * DG * D_DIM / 4)     // float4 count of Wd (== Wu)

// ---------------- scratch (device globals; no runtime allocs) ----------------
__device__ uint16_t g_xh[(size_t)T_TOK * D_DIM];
__device__ uint16_t g_xl[(size_t)T_TOK * D_DIM];
__device__ uint16_t g_wdh[(size_t)E_NUM * DG * D_DIM];
__device__ uint16_t g_wdl[(size_t)E_NUM * DG * D_DIM];
__device__ uint16_t g_wuh[(size_t)E_NUM * D_DIM * DG];
__device__ uint16_t g_wul[(size_t)E_NUM * D_DIM * DG];
__device__ uint16_t g_dnh[(size_t)T_TOK * DG];
__device__ uint16_t g_dnl[(size_t)T_TOK * DG];
__device__ float  g_S2[2 * T_TOK * E_NUM];             // partial gate scores
__device__ int    g_list[E_NUM * T_TOK];
__device__ float  g_gatel[E_NUM * T_TOK];
__device__ int    g_cnt[E_NUM];
__device__ float  g_down_s[2 * T_TOK * DG];            // [tok2][DG]
__device__ float  g_up_s[(size_t)2 * T_TOK * D_DIM];   // [tok2][D]

// ---------------- PTX helpers (all baseline sm_80/90 PTX) ----------------
__device__ __forceinline__ uint32_t smem_u32(const void* p) {
    uint32_t a;
    asm("{ .reg .u64 t; cvta.to.shared.u64 t, %1; cvt.u32.u64 %0, t; }" : "=r"(a) : "l"(p));
    return a;
}
__device__ __forceinline__ void cpa16(uint32_t s, const void* g) {
    asm volatile("cp.async.cg.shared.global [%0], [%1], 16;" :: "r"(s), "l"(g));
}
#define CP_COMMIT() asm volatile("cp.async.commit_group;" ::: "memory")
#define CP_WAIT2()  asm volatile("cp.async.wait_group 2;" ::: "memory")

__device__ __forceinline__ void ldsm4(uint32_t* r, uint32_t addr) {
    asm volatile("ldmatrix.sync.aligned.m8n8.x4.shared.b16 {%0,%1,%2,%3}, [%4];"
                 : "=r"(r[0]), "=r"(r[1]), "=r"(r[2]), "=r"(r[3]) : "r"(addr));
}
__device__ __forceinline__ void mma16816(float* c, const uint32_t* a,
                                         uint32_t b0, uint32_t b1) {
    asm volatile(
        "mma.sync.aligned.m16n8k16.row.col.f32.bf16.bf16.f32 "
        "{%0,%1,%2,%3}, {%4,%5,%6,%7}, {%8,%9}, {%0,%1,%2,%3};"
        : "+f"(c[0]), "+f"(c[1]), "+f"(c[2]), "+f"(c[3])
        : "r"(a[0]), "r"(a[1]), "r"(a[2]), "r"(a[3]), "r"(b0), "r"(b1));
}

// ---------------- 1) merged split conversion fp32 -> bf16 hi/lo ----------------
__device__ __forceinline__ uint16_t bfr(__nv_bfloat16 h) {
    return *reinterpret_cast<uint16_t*>(&h);
}
__device__ __forceinline__ void split_store(float4 v, uint2* hi, uint2* lo, int j) {
    __nv_bfloat16 h0 = __float2bfloat16(v.x), h1 = __float2bfloat16(v.y),
                  h2 = __float2bfloat16(v.z), h3 = __float2bfloat16(v.w);
    __nv_bfloat16 l0 = __float2bfloat16(v.x - __bfloat162float(h0));
    __nv_bfloat16 l1 = __float2bfloat16(v.y - __bfloat162float(h1));
    __nv_bfloat16 l2 = __float2bfloat16(v.z - __bfloat162float(h2));
    __nv_bfloat16 l3 = __float2bfloat16(v.w - __bfloat162float(h3));
    uint2 H, L;
    H.x = (uint32_t)bfr(h0) | ((uint32_t)bfr(h1) << 16);
    H.y = (uint32_t)bfr(h2) | ((uint32_t)bfr(h3) << 16);
    L.x = (uint32_t)bfr(l0) | ((uint32_t)bfr(l1) << 16);
    L.y = (uint32_t)bfr(l2) | ((uint32_t)bfr(l3) << 16);
    hi[j] = H; lo[j] = L;
}
__global__ void __launch_bounds__(256) conv_all(const float4* __restrict__ x,
                                                const float4* __restrict__ wd,
                                                const float4* __restrict__ wu) {
    int i = blockIdx.x * 256 + threadIdx.x;
    if (i < NX4) {
        split_store(x[i], (uint2*)g_xh, (uint2*)g_xl, i);
    } else if (i < NX4 + NW4) {
        int j = i - NX4;
        split_store(wd[j], (uint2*)g_wdh, (uint2*)g_wdl, j);
    } else {
        int j = i - NX4 - NW4;
        split_store(wu[j], (uint2*)g_wuh, (uint2*)g_wul, j);
    }
}

// ---------------- 2) gating partial dots: S2[half][t][e] ----------------
// grid (T/32, 2), 256 threads. Wg half staged in smem; warp-per-token.
__global__ void __launch_bounds__(256) gate_partial(const float* __restrict__ x,
                                                    const float* __restrict__ Wg) {
    __shared__ float wgs[E_NUM * 1024];
    int half = blockIdx.y;
    int t0 = blockIdx.x * 32;
    int tid = threadIdx.x;
    // stage Wg[e][half*1024 .. +1024) : 8192 floats
    {
        const float4* src = (const float4*)Wg;
        float4* dst = (float4*)wgs;
        #pragma unroll
        for (int r = 0; r < 8; r++) {
            int idx = r * 256 + tid;            // [0,2048) float4s
            int e = idx >> 8, c = idx & 255;
            dst[idx] = src[e * 512 + half * 256 + c];
        }
    }
    __syncthreads();
    int w = tid >> 5, lane = tid & 31;
    const float4* wv4 = (const float4*)wgs;
    #pragma unroll
    for (int j = 0; j < 4; j++) {
        int t = t0 + w * 4 + j;
        const float4* xr = (const float4*)(x + (size_t)t * D_DIM + half * 1024);
        float acc[E_NUM];
        #pragma unroll
        for (int e = 0; e < E_NUM; e++) acc[e] = 0.f;
        #pragma unroll
        for (int it = 0; it < 8; it++) {
            float4 xv = xr[it * 32 + lane];
            #pragma unroll
            for (int e = 0; e < E_NUM; e++) {
                float4 wv = wv4[e * 256 + it * 32 + lane];
                acc[e] += xv.x * wv.x + xv.y * wv.y + xv.z * wv.z + xv.w * wv.w;
            }
        }
        #pragma unroll
        for (int e = 0; e < E_NUM; e++) {
            float p = acc[e];
            #pragma unroll
            for (int o = 16; o; o >>= 1) p += __shfl_down_sync(0xffffffffu, p, o);
            acc[e] = p;
        }
        if (lane == 0) {
            #pragma unroll
            for (int e = 0; e < E_NUM; e++)
                g_S2[(half * T_TOK + t) * E_NUM + e] = acc[e];
        }
    }
}

// ---------------- 3) top-2 + deterministic per-expert compaction ----------------
__global__ void __launch_bounds__(256) build_lists() {
    int e = blockIdx.x, tid = threadIdx.x;
    int wid = tid >> 5, lane = tid & 31;
    __shared__ int sbase;
    __shared__ int wtot[8];
    if (tid == 0) sbase = 0;
    __syncthreads();
    for (int t0 = 0; t0 < T_TOK; t0 += 256) {
        int t = t0 + tid;
        // recompute sigmoid + top2 from partial sums (cheap, redundant per block)
        const float4* p0 = (const float4*)(g_S2 + (size_t)t * E_NUM);
        const float4* p1 = (const float4*)(g_S2 + (size_t)(T_TOK + t) * E_NUM);
        float4 a0 = p0[0], a1 = p0[1], b0v = p1[0], b1v = p1[1];
        float sv[E_NUM];
        sv[0] = a0.x + b0v.x; sv[1] = a0.y + b0v.y; sv[2] = a0.z + b0v.z; sv[3] = a0.w + b0v.w;
        sv[4] = a1.x + b1v.x; sv[5] = a1.y + b1v.y; sv[6] = a1.z + b1v.z; sv[7] = a1.w + b1v.w;
        #pragma unroll
        for (int k = 0; k < E_NUM; k++) sv[k] = 1.f / (1.f + expf(-sv[k]));
        int i0 = 0; float v0 = sv[0];
        #pragma unroll
        for (int k = 1; k < E_NUM; k++) if (sv[k] > v0) { v0 = sv[k]; i0 = k; }
        int i1 = -1; float v1 = -1.f;
        #pragma unroll
        for (int k = 0; k < E_NUM; k++) if (k != i0 && sv[k] > v1) { v1 = sv[k]; i1 = k; }

        int slot = -1; float g = 0.f;
        if (i0 == e) { slot = 0; g = v0; }
        else if (i1 == e) { slot = 1; g = v1; }
        bool flag = (slot >= 0);
        unsigned bal = __ballot_sync(0xffffffffu, flag);
        int wp = __popc(bal & ((1u << lane) - 1u));
        if (lane == 0) wtot[wid] = __popc(bal);
        __syncthreads();
        int off = 0;
        for (int i = 0; i < wid; i++) off += wtot[i];
        int tot = 0;
        for (int i = 0; i < 8; i++) tot += wtot[i];
        int base = sbase;
        if (flag) {
            int pos = base + off + wp;
            g_list[e * T_TOK + pos]  = t * 2 + slot;
            g_gatel[e * T_TOK + pos] = g;
        }
        __syncthreads();
        if (tid == 0) sbase = base + tot;
        __syncthreads();
    }
    if (tid == 0) g_cnt[e] = sbase;
}

// ---------------- 4) grouped GEMM: mma.sync bf16 x3, cp.async 4-stage ----------
// Templated on BN (64 for down GEMM fill, 128 for up GEMM reuse).
template <int BNT>
__global__ void __launch_bounds__(256) moe_gemm_mma(
    const uint16_t* __restrict__ Ah, const uint16_t* __restrict__ Al, int lda,
    const uint16_t* __restrict__ Bh, const uint16_t* __restrict__ Bl,
    int K, int Nfull, float* __restrict__ outS) {
    constexpr int BMATB = BNT * ROWB;                 // B tile bytes
    constexpr int STGB  = 2 * MATB + 2 * BMATB;       // stage bytes
    constexpr int NJ    = BNT / 16;                   // n frags per warp
    constexpr int NGQ   = BNT / 32;                   // ldsm groups for B
    extern __shared__ char smem[];
    __shared__ int   stok[BM];
    __shared__ float sgate[BM];

    int e = blockIdx.z;
    int cnt = g_cnt[e];
    int m0 = blockIdx.x * BM;
    if (m0 >= cnt) return;
    int nbase = blockIdx.y * BNT;
    int tid = threadIdx.x;

    if (tid < BM) {
        int r = m0 + tid;
        if (r < cnt) { stok[tid] = g_list[e * T_TOK + r]; sgate[tid] = g_gatel[e * T_TOK + r]; }
        else         { stok[tid] = 0;                     sgate[tid] = 0.f; }
    }
    __syncthreads();

    // cp.async roles
    int srow = tid >> 1, q = tid & 1;                 // A rows: all 256 threads
    int tokrow = stok[srow] >> 1;
    const uint16_t* gAh = Ah + (size_t)tokrow * lda + q * 8;
    const uint16_t* gAl = Al + (size_t)tokrow * lda + q * 8;
    bool doB = (BNT == 128) || (tid < 128);           // B rows: first 2*BNT threads
    int brow = (tid & (2 * BNT - 1)) >> 1;
    size_t bro = ((size_t)e * Nfull + nbase + brow) * K + q * 8;
    const uint16_t* gBh = Bh + bro;
    const uint16_t* gBl = Bl + bro;
    uint32_t smb = smem_u32(smem);
    uint32_t soA = (uint32_t)srow * ROWB + (uint32_t)q * 16;
    uint32_t soB = (uint32_t)brow * ROWB + (uint32_t)q * 16;

    int C = K / BK;
    #pragma unroll
    for (int s = 0; s < STAGES - 1; s++) {
        if (s < C) {
            uint32_t sb = smb + s * STGB;
            int k0 = s * BK;
            cpa16(sb + soA,        gAh + k0);
            cpa16(sb + MATB + soA, gAl + k0);
            if (doB) {
                cpa16(sb + 2 * MATB + soB,         gBh + k0);
                cpa16(sb + 2 * MATB + BMATB + soB, gBl + k0);
            }
        }
        CP_COMMIT();
    }

    int wid = tid >> 5, lane = tid & 31;
    int wm = (wid & 3) * 32;              // 4 warps along M
    int wn = (wid >> 2) * (BNT / 2);      // 2 warps along N
    uint32_t lrow = (uint32_t)(lane & 15);
    uint32_t lkb  = (uint32_t)(lane >> 4) * 16;

    float acc[2][NJ][4];
    #pragma unroll
    for (int i = 0; i < 2; i++)
        #pragma unroll
        for (int j = 0; j < NJ; j++)
            #pragma unroll
            for (int v = 0; v < 4; v++) acc[i][j][v] = 0.f;

    #pragma unroll 1
    for (int c = 0; c < C; c++) {
        CP_WAIT2();
        __syncthreads();
        uint32_t sb = smb + (uint32_t)(c & (STAGES - 1)) * STGB;

        uint32_t ah[2][4], al[2][4], bh[NGQ][4], bl[NGQ][4];
        #pragma unroll
        for (int i = 0; i < 2; i++) {
            uint32_t a = sb + (wm + i * 16 + lrow) * ROWB + lkb;
            ldsm4(ah[i], a);
            ldsm4(al[i], a + MATB);
        }
        #pragma unroll
        for (int gq = 0; gq < NGQ; gq++) {
            uint32_t a = sb + 2 * MATB + (wn + gq * 16 + lrow) * ROWB + lkb;
            ldsm4(bh[gq], a);
            ldsm4(bl[gq], a + BMATB);
        }
        #pragma unroll
        for (int i = 0; i < 2; i++)
            #pragma unroll
            for (int j = 0; j < NJ; j++) {
                int gq = j >> 1, o = j & 1;
                uint32_t b0h = bh[gq][o], b1h = bh[gq][o + 2];
                mma16816(acc[i][j], ah[i], b0h, b1h);
                mma16816(acc[i][j], ah[i], bl[gq][o], bl[gq][o + 2]);
                mma16816(acc[i][j], al[i], b0h, b1h);
            }

        int nc = c + STAGES - 1;
        if (nc < C) {
            uint32_t sb2 = smb + (uint32_t)(nc & (STAGES - 1)) * STGB;
            int k0 = nc * BK;
            cpa16(sb2 + soA,        gAh + k0);
            cpa16(sb2 + MATB + soA, gAl + k0);
            if (doB) {
                cpa16(sb2 + 2 * MATB + soB,         gBh + k0);
                cpa16(sb2 + 2 * MATB + BMATB + soB, gBl + k0);
            }
        }
        CP_COMMIT();
    }

    // epilogue: gate-scale, exclusive (token,slot) scatter
    #pragma unroll
    for (int i = 0; i < 2; i++) {
        #pragma unroll
        for (int half = 0; half < 2; half++) {
            int mloc = wm + i * 16 + (lane >> 2) + half * 8;
            if (m0 + mloc >= cnt) continue;
            int tk2 = stok[mloc];
            float g = sgate[mloc];
            float* orow = outS + (size_t)tk2 * Nfull + nbase + wn + (lane & 3) * 2;
            #pragma unroll
            for (int j = 0; j < NJ; j++) {
                float2 v;
                v.x = g * acc[i][j][half * 2 + 0];
                v.y = g * acc[i][j][half * 2 + 1];
                *(float2*)(orow + j * 8) = v;
            }
        }
    }
}

// ---------------- 5) combine down slots + split to bf16 hi/lo ----------------
__global__ void __launch_bounds__(256) combine_down_split() {
    int i = blockIdx.x * 256 + threadIdx.x;   // over T_TOK*DG/4
    int t = i >> 6, c4 = i & 63;
    const float4* s = (const float4*)g_down_s;
    float4 a = s[t * 128 + c4];
    float4 b = s[t * 128 + 64 + c4];
    float4 v = make_float4(a.x + b.x, a.y + b.y, a.z + b.z, a.w + b.w);
    split_store(v, (uint2*)g_dnh, (uint2*)g_dnl, i);
}

// ---------------- 6) combine up slots -> output ----------------
__global__ void __launch_bounds__(256) combine_up(float* __restrict__ out) {
    int i = blockIdx.x * 256 + threadIdx.x;   // over (T_TOK*D)/4
    int t = i >> 9, d4 = i & 511;
    const float4* a = (const float4*)(g_up_s + (size_t)t * 2 * D_DIM) + d4;
    const float4* b = (const float4*)(g_up_s + (size_t)t * 2 * D_DIM + D_DIM) + d4;
    float4 va = *a, vb = *b;
    ((float4*)out)[i] = make_float4(va.x + vb.x, va.y + vb.y, va.z + vb.z, va.w + vb.w);
}

// ---------------- launcher ----------------
extern "C" void kernel_launch(void* const* d_in, const int* in_sizes, int n_in,
                              void* d_out, int out_size) {
    const float* x  = (const float*)d_in[0];
    const float* Wg = (const float*)d_in[1];
    const float* Wd = (const float*)d_in[2];
    const float* Wu = (const float*)d_in[3];
    float* out = (float*)d_out;

    constexpr int SMEM64  = STAGES * (2 * MATB + 2 * 64 * ROWB);    // 73728
    constexpr int SMEM128 = STAGES * (2 * MATB + 2 * 128 * ROWB);   // 98304
    cudaFuncSetAttribute(moe_gemm_mma<64>,  cudaFuncAttributeMaxDynamicSharedMemorySize, SMEM64);
    cudaFuncSetAttribute(moe_gemm_mma<128>, cudaFuncAttributeMaxDynamicSharedMemorySize, SMEM128);

    void *p_xh, *p_xl, *p_wdh, *p_wdl, *p_wuh, *p_wul, *p_dnh, *p_dnl, *p_ds, *p_us;
    cudaGetSymbolAddress(&p_xh, g_xh);   cudaGetSymbolAddress(&p_xl, g_xl);
    cudaGetSymbolAddress(&p_wdh, g_wdh); cudaGetSymbolAddress(&p_wdl, g_wdl);
    cudaGetSymbolAddress(&p_wuh, g_wuh); cudaGetSymbolAddress(&p_wul, g_wul);
    cudaGetSymbolAddress(&p_dnh, g_dnh); cudaGetSymbolAddress(&p_dnl, g_dnl);
    cudaGetSymbolAddress(&p_ds, g_down_s); cudaGetSymbolAddress(&p_us, g_up_s);

    // 1) merged conversions   2) gate partials   3) top2 + lists
    conv_all<<<(NX4 + 2 * NW4) / 256, 256>>>((const float4*)x, (const float4*)Wd, (const float4*)Wu);
    gate_partial<<<dim3(T_TOK / 32, 2), 256>>>(x, Wg);
    build_lists<<<E_NUM, 256>>>();

    // 4) down: A = split(x) gathered [T,2048], B = split(Wd) [E][256][2048], BN=64
    moe_gemm_mma<64><<<dim3(T_TOK / BM, DG / 64, E_NUM), 256, SMEM64>>>(
        (const uint16_t*)p_xh, (const uint16_t*)p_xl, D_DIM,
        (const uint16_t*)p_wdh, (const uint16_t*)p_wdl, D_DIM, DG, (float*)p_ds);
    combine_down_split<<<(T_TOK * DG / 4) / 256, 256>>>();

    // 6) up: A = split(down) gathered [T,256], B = split(Wu) [E][2048][256], BN=128
    moe_gemm_mma<128><<<dim3(T_TOK / BM, D_DIM / 128, E_NUM), 256, SMEM128>>>(
        (const uint16_t*)p_dnh, (const uint16_t*)p_dnl, DG,
        (const uint16_t*)p_wuh, (const uint16_t*)p_wul, DG, D_DIM, (float*)p_us);
    combine_up<<<(T_TOK * D_DIM / 4) / 256, 256>>>(out);
}

// round 6
// speedup vs baseline: 3.1630x; 1.1098x over previous
#include <cuda_runtime.h>
#include <cuda_bf16.h>
#include <cstdint>

#define T_TOK 4096
#define D_DIM 2048
#define E_NUM 8
#define DG    256

#define BM 128
#define BK 16
#define STAGES 4
#define ROWB 32                       // smem bytes per row (no pad; XOR swizzle)
#define MATB (128 * ROWB)             // 4096 bytes per 128-row matrix tile

#define NX4  (T_TOK * D_DIM / 4)          // float4 count of x
#define NW4  (E_NUM * DG * D_DIM / 4)     // float4 count of Wd (== Wu)

// ---------------- scratch (device globals; no runtime allocs) ----------------
__device__ uint16_t g_xh[(size_t)T_TOK * D_DIM];
__device__ uint16_t g_xl[(size_t)T_TOK * D_DIM];
__device__ uint16_t g_wdh[(size_t)E_NUM * DG * D_DIM];
__device__ uint16_t g_wdl[(size_t)E_NUM * DG * D_DIM];
__device__ uint16_t g_wuh[(size_t)E_NUM * D_DIM * DG];
__device__ uint16_t g_wul[(size_t)E_NUM * D_DIM * DG];
__device__ uint16_t g_dnh[(size_t)T_TOK * DG];
__device__ uint16_t g_dnl[(size_t)T_TOK * DG];
__device__ float  g_S2[2 * T_TOK * E_NUM];             // partial gate scores
__device__ int    g_list[E_NUM * T_TOK];
__device__ float  g_gatel[E_NUM * T_TOK];
__device__ int    g_cnt[E_NUM];
__device__ float  g_down_s[2 * T_TOK * DG];            // [tok2][DG]
__device__ float  g_up_s[(size_t)2 * T_TOK * D_DIM];   // [tok2][D]

// ---------------- PTX helpers (all baseline sm_80/90 PTX) ----------------
__device__ __forceinline__ uint32_t smem_u32(const void* p) {
    uint32_t a;
    asm("{ .reg .u64 t; cvta.to.shared.u64 t, %1; cvt.u32.u64 %0, t; }" : "=r"(a) : "l"(p));
    return a;
}
__device__ __forceinline__ void cpa16(uint32_t s, const void* g) {
    asm volatile("cp.async.cg.shared.global [%0], [%1], 16;" :: "r"(s), "l"(g));
}
#define CP_COMMIT() asm volatile("cp.async.commit_group;" ::: "memory")
#define CP_WAIT2()  asm volatile("cp.async.wait_group 2;" ::: "memory")

__device__ __forceinline__ void ldsm4(uint32_t* r, uint32_t addr) {
    asm volatile("ldmatrix.sync.aligned.m8n8.x4.shared.b16 {%0,%1,%2,%3}, [%4];"
                 : "=r"(r[0]), "=r"(r[1]), "=r"(r[2]), "=r"(r[3]) : "r"(addr));
}
__device__ __forceinline__ void mma16816(float* c, const uint32_t* a,
                                         uint32_t b0, uint32_t b1) {
    asm volatile(
        "mma.sync.aligned.m16n8k16.row.col.f32.bf16.bf16.f32 "
        "{%0,%1,%2,%3}, {%4,%5,%6,%7}, {%8,%9}, {%0,%1,%2,%3};"
        : "+f"(c[0]), "+f"(c[1]), "+f"(c[2]), "+f"(c[3])
        : "r"(a[0]), "r"(a[1]), "r"(a[2]), "r"(a[3]), "r"(b0), "r"(b1));
}

// ---------------- 1) merged split conversion fp32 -> bf16 hi/lo ----------------
__device__ __forceinline__ uint16_t bfr(__nv_bfloat16 h) {
    return *reinterpret_cast<uint16_t*>(&h);
}
__device__ __forceinline__ void split_store(float4 v, uint2* hi, uint2* lo, int j) {
    __nv_bfloat16 h0 = __float2bfloat16(v.x), h1 = __float2bfloat16(v.y),
                  h2 = __float2bfloat16(v.z), h3 = __float2bfloat16(v.w);
    __nv_bfloat16 l0 = __float2bfloat16(v.x - __bfloat162float(h0));
    __nv_bfloat16 l1 = __float2bfloat16(v.y - __bfloat162float(h1));
    __nv_bfloat16 l2 = __float2bfloat16(v.z - __bfloat162float(h2));
    __nv_bfloat16 l3 = __float2bfloat16(v.w - __bfloat162float(h3));
    uint2 H, L;
    H.x = (uint32_t)bfr(h0) | ((uint32_t)bfr(h1) << 16);
    H.y = (uint32_t)bfr(h2) | ((uint32_t)bfr(h3) << 16);
    L.x = (uint32_t)bfr(l0) | ((uint32_t)bfr(l1) << 16);
    L.y = (uint32_t)bfr(l2) | ((uint32_t)bfr(l3) << 16);
    hi[j] = H; lo[j] = L;
}
__global__ void __launch_bounds__(256) conv_all(const float4* __restrict__ x,
                                                const float4* __restrict__ wd,
                                                const float4* __restrict__ wu) {
    int i = blockIdx.x * 256 + threadIdx.x;
    if (i < NX4) {
        split_store(x[i], (uint2*)g_xh, (uint2*)g_xl, i);
    } else if (i < NX4 + NW4) {
        int j = i - NX4;
        split_store(wd[j], (uint2*)g_wdh, (uint2*)g_wdl, j);
    } else {
        int j = i - NX4 - NW4;
        split_store(wu[j], (uint2*)g_wuh, (uint2*)g_wul, j);
    }
}

// ---------------- 2) gating partial dots: S2[half][t][e] ----------------
__global__ void __launch_bounds__(256) gate_partial(const float* __restrict__ x,
                                                    const float* __restrict__ Wg) {
    __shared__ float wgs[E_NUM * 1024];
    int half = blockIdx.y;
    int t0 = blockIdx.x * 32;
    int tid = threadIdx.x;
    {
        const float4* src = (const float4*)Wg;
        float4* dst = (float4*)wgs;
        #pragma unroll
        for (int r = 0; r < 8; r++) {
            int idx = r * 256 + tid;
            int e = idx >> 8, c = idx & 255;
            dst[idx] = src[e * 512 + half * 256 + c];
        }
    }
    __syncthreads();
    int w = tid >> 5, lane = tid & 31;
    const float4* wv4 = (const float4*)wgs;
    #pragma unroll
    for (int j = 0; j < 4; j++) {
        int t = t0 + w * 4 + j;
        const float4* xr = (const float4*)(x + (size_t)t * D_DIM + half * 1024);
        float acc[E_NUM];
        #pragma unroll
        for (int e = 0; e < E_NUM; e++) acc[e] = 0.f;
        #pragma unroll
        for (int it = 0; it < 8; it++) {
            float4 xv = xr[it * 32 + lane];
            #pragma unroll
            for (int e = 0; e < E_NUM; e++) {
                float4 wv = wv4[e * 256 + it * 32 + lane];
                acc[e] += xv.x * wv.x + xv.y * wv.y + xv.z * wv.z + xv.w * wv.w;
            }
        }
        #pragma unroll
        for (int e = 0; e < E_NUM; e++) {
            float p = acc[e];
            #pragma unroll
            for (int o = 16; o; o >>= 1) p += __shfl_down_sync(0xffffffffu, p, o);
            acc[e] = p;
        }
        if (lane == 0) {
            #pragma unroll
            for (int e = 0; e < E_NUM; e++)
                g_S2[(half * T_TOK + t) * E_NUM + e] = acc[e];
        }
    }
}

// ---------------- 3) top-2 + deterministic per-expert compaction ----------------
__global__ void __launch_bounds__(256) build_lists() {
    int e = blockIdx.x, tid = threadIdx.x;
    int wid = tid >> 5, lane = tid & 31;
    __shared__ int sbase;
    __shared__ int wtot[8];
    if (tid == 0) sbase = 0;
    __syncthreads();
    for (int t0 = 0; t0 < T_TOK; t0 += 256) {
        int t = t0 + tid;
        const float4* p0 = (const float4*)(g_S2 + (size_t)t * E_NUM);
        const float4* p1 = (const float4*)(g_S2 + (size_t)(T_TOK + t) * E_NUM);
        float4 a0 = p0[0], a1 = p0[1], b0v = p1[0], b1v = p1[1];
        float sv[E_NUM];
        sv[0] = a0.x + b0v.x; sv[1] = a0.y + b0v.y; sv[2] = a0.z + b0v.z; sv[3] = a0.w + b0v.w;
        sv[4] = a1.x + b1v.x; sv[5] = a1.y + b1v.y; sv[6] = a1.z + b1v.z; sv[7] = a1.w + b1v.w;
        #pragma unroll
        for (int k = 0; k < E_NUM; k++) sv[k] = 1.f / (1.f + expf(-sv[k]));
        int i0 = 0; float v0 = sv[0];
        #pragma unroll
        for (int k = 1; k < E_NUM; k++) if (sv[k] > v0) { v0 = sv[k]; i0 = k; }
        int i1 = -1; float v1 = -1.f;
        #pragma unroll
        for (int k = 0; k < E_NUM; k++) if (k != i0 && sv[k] > v1) { v1 = sv[k]; i1 = k; }

        int slot = -1; float g = 0.f;
        if (i0 == e) { slot = 0; g = v0; }
        else if (i1 == e) { slot = 1; g = v1; }
        bool flag = (slot >= 0);
        unsigned bal = __ballot_sync(0xffffffffu, flag);
        int wp = __popc(bal & ((1u << lane) - 1u));
        if (lane == 0) wtot[wid] = __popc(bal);
        __syncthreads();
        int off = 0;
        for (int i = 0; i < wid; i++) off += wtot[i];
        int tot = 0;
        for (int i = 0; i < 8; i++) tot += wtot[i];
        int base = sbase;
        if (flag) {
            int pos = base + off + wp;
            g_list[e * T_TOK + pos]  = t * 2 + slot;
            g_gatel[e * T_TOK + pos] = g;
        }
        __syncthreads();
        if (tid == 0) sbase = base + tot;
        __syncthreads();
    }
    if (tid == 0) g_cnt[e] = sbase;
}

// ---------------- 4) grouped GEMM: mma.sync bf16 x3, cp.async 4-stage ----------
// 32B rows + XOR swizzle of the 16B k-half (half ^= (row>>2)&1): conflict-free
// stores and ldmatrix with zero padding. BN=64 for both GEMMs (occupancy).
template <int BNT>
__global__ void __launch_bounds__(256) moe_gemm_mma(
    const uint16_t* __restrict__ Ah, const uint16_t* __restrict__ Al, int lda,
    const uint16_t* __restrict__ Bh, const uint16_t* __restrict__ Bl,
    int K, int Nfull, float* __restrict__ outS) {
    constexpr int BMATB = BNT * ROWB;
    constexpr int STGB  = 2 * MATB + 2 * BMATB;
    constexpr int NJ    = BNT / 16;
    constexpr int NGQ   = BNT / 32;
    extern __shared__ char smem[];
    __shared__ int   stok[BM];
    __shared__ float sgate[BM];

    int e = blockIdx.z;
    int cnt = g_cnt[e];
    int m0 = blockIdx.x * BM;
    if (m0 >= cnt) return;
    int nbase = blockIdx.y * BNT;
    int tid = threadIdx.x;

    if (tid < BM) {
        int r = m0 + tid;
        if (r < cnt) { stok[tid] = g_list[e * T_TOK + r]; sgate[tid] = g_gatel[e * T_TOK + r]; }
        else         { stok[tid] = 0;                     sgate[tid] = 0.f; }
    }
    __syncthreads();

    // cp.async roles (store with swizzled 16B-half)
    int srow = tid >> 1, q = tid & 1;
    int tokrow = stok[srow] >> 1;
    const uint16_t* gAh = Ah + (size_t)tokrow * lda + q * 8;
    const uint16_t* gAl = Al + (size_t)tokrow * lda + q * 8;
    bool doB = tid < 2 * BNT;
    int brow = (tid & (2 * BNT - 1)) >> 1;
    size_t bro = ((size_t)e * Nfull + nbase + brow) * K + q * 8;
    const uint16_t* gBh = Bh + bro;
    const uint16_t* gBl = Bl + bro;
    uint32_t smb = smem_u32(smem);
    uint32_t soA = (uint32_t)srow * ROWB + (((uint32_t)(q ^ (srow >> 2)) & 1u) << 4);
    uint32_t soB = (uint32_t)brow * ROWB + (((uint32_t)(q ^ (brow >> 2)) & 1u) << 4);

    int C = K / BK;
    #pragma unroll
    for (int s = 0; s < STAGES - 1; s++) {
        if (s < C) {
            uint32_t sb = smb + s * STGB;
            int k0 = s * BK;
            cpa16(sb + soA,        gAh + k0);
            cpa16(sb + MATB + soA, gAl + k0);
            if (doB) {
                cpa16(sb + 2 * MATB + soB,         gBh + k0);
                cpa16(sb + 2 * MATB + BMATB + soB, gBl + k0);
            }
        }
        CP_COMMIT();
    }

    int wid = tid >> 5, lane = tid & 31;
    int wm = (wid & 3) * 32;              // 4 warps along M
    int wn = (wid >> 2) * (BNT / 2);      // 2 warps along N
    uint32_t lrow = (uint32_t)(lane & 15);
    // swizzled per-thread 16B-half offset: (lane>>4) ^ bit2 of the row (= lane bit2)
    uint32_t swz = ((((uint32_t)lane >> 4) ^ ((uint32_t)lane >> 2)) & 1u) << 4;

    float acc[2][NJ][4];
    #pragma unroll
    for (int i = 0; i < 2; i++)
        #pragma unroll
        for (int j = 0; j < NJ; j++)
            #pragma unroll
            for (int v = 0; v < 4; v++) acc[i][j][v] = 0.f;

    #pragma unroll 1
    for (int c = 0; c < C; c++) {
        CP_WAIT2();
        __syncthreads();
        uint32_t sb = smb + (uint32_t)(c & (STAGES - 1)) * STGB;

        uint32_t ah[2][4], al[2][4], bh[NGQ][4], bl[NGQ][4];
        #pragma unroll
        for (int i = 0; i < 2; i++) {
            uint32_t a = sb + (wm + i * 16 + lrow) * ROWB + swz;
            ldsm4(ah[i], a);
            ldsm4(al[i], a + MATB);
        }
        #pragma unroll
        for (int gq = 0; gq < NGQ; gq++) {
            uint32_t a = sb + 2 * MATB + (wn + gq * 16 + lrow) * ROWB + swz;
            ldsm4(bh[gq], a);
            ldsm4(bl[gq], a + BMATB);
        }
        // term 1: Ah*Bh for all (i,j), then cross terms — breaks RAW chains
        #pragma unroll
        for (int i = 0; i < 2; i++)
            #pragma unroll
            for (int j = 0; j < NJ; j++) {
                int gq = j >> 1, o = j & 1;
                mma16816(acc[i][j], ah[i], bh[gq][o], bh[gq][o + 2]);
            }
        #pragma unroll
        for (int i = 0; i < 2; i++)
            #pragma unroll
            for (int j = 0; j < NJ; j++) {
                int gq = j >> 1, o = j & 1;
                mma16816(acc[i][j], ah[i], bl[gq][o], bl[gq][o + 2]);
            }
        #pragma unroll
        for (int i = 0; i < 2; i++)
            #pragma unroll
            for (int j = 0; j < NJ; j++) {
                int gq = j >> 1, o = j & 1;
                mma16816(acc[i][j], al[i], bh[gq][o], bh[gq][o + 2]);
            }

        int nc = c + STAGES - 1;
        if (nc < C) {
            uint32_t sb2 = smb + (uint32_t)(nc & (STAGES - 1)) * STGB;
            int k0 = nc * BK;
            cpa16(sb2 + soA,        gAh + k0);
            cpa16(sb2 + MATB + soA, gAl + k0);
            if (doB) {
                cpa16(sb2 + 2 * MATB + soB,         gBh + k0);
                cpa16(sb2 + 2 * MATB + BMATB + soB, gBl + k0);
            }
        }
        CP_COMMIT();
    }

    // epilogue: gate-scale, exclusive (token,slot) scatter
    #pragma unroll
    for (int i = 0; i < 2; i++) {
        #pragma unroll
        for (int half = 0; half < 2; half++) {
            int mloc = wm + i * 16 + (lane >> 2) + half * 8;
            if (m0 + mloc >= cnt) continue;
            int tk2 = stok[mloc];
            float g = sgate[mloc];
            float* orow = outS + (size_t)tk2 * Nfull + nbase + wn + (lane & 3) * 2;
            #pragma unroll
            for (int j = 0; j < NJ; j++) {
                float2 v;
                v.x = g * acc[i][j][half * 2 + 0];
                v.y = g * acc[i][j][half * 2 + 1];
                *(float2*)(orow + j * 8) = v;
            }
        }
    }
}

// ---------------- 5) combine down slots + split to bf16 hi/lo ----------------
__global__ void __launch_bounds__(256) combine_down_split() {
    int i = blockIdx.x * 256 + threadIdx.x;   // over T_TOK*DG/4
    int t = i >> 6, c4 = i & 63;
    const float4* s = (const float4*)g_down_s;
    float4 a = s[t * 128 + c4];
    float4 b = s[t * 128 + 64 + c4];
    float4 v = make_float4(a.x + b.x, a.y + b.y, a.z + b.z, a.w + b.w);
    split_store(v, (uint2*)g_dnh, (uint2*)g_dnl, i);
}

// ---------------- 6) combine up slots -> output ----------------
__global__ void __launch_bounds__(256) combine_up(float* __restrict__ out) {
    int i = blockIdx.x * 256 + threadIdx.x;   // over (T_TOK*D)/4
    int t = i >> 9, d4 = i & 511;
    const float4* a = (const float4*)(g_up_s + (size_t)t * 2 * D_DIM) + d4;
    const float4* b = (const float4*)(g_up_s + (size_t)t * 2 * D_DIM + D_DIM) + d4;
    float4 va = *a, vb = *b;
    ((float4*)out)[i] = make_float4(va.x + vb.x, va.y + vb.y, va.z + vb.z, va.w + vb.w);
}

// ---------------- launcher ----------------
extern "C" void kernel_launch(void* const* d_in, const int* in_sizes, int n_in,
                              void* d_out, int out_size) {
    const float* x  = (const float*)d_in[0];
    const float* Wg = (const float*)d_in[1];
    const float* Wd = (const float*)d_in[2];
    const float* Wu = (const float*)d_in[3];
    float* out = (float*)d_out;

    constexpr int SMEM64 = STAGES * (2 * MATB + 2 * 64 * ROWB);    // 49152
    cudaFuncSetAttribute(moe_gemm_mma<64>, cudaFuncAttributeMaxDynamicSharedMemorySize, SMEM64);

    void *p_xh, *p_xl, *p_wdh, *p_wdl, *p_wuh, *p_wul, *p_dnh, *p_dnl, *p_ds, *p_us;
    cudaGetSymbolAddress(&p_xh, g_xh);   cudaGetSymbolAddress(&p_xl, g_xl);
    cudaGetSymbolAddress(&p_wdh, g_wdh); cudaGetSymbolAddress(&p_wdl, g_wdl);
    cudaGetSymbolAddress(&p_wuh, g_wuh); cudaGetSymbolAddress(&p_wul, g_wul);
    cudaGetSymbolAddress(&p_dnh, g_dnh); cudaGetSymbolAddress(&p_dnl, g_dnl);
    cudaGetSymbolAddress(&p_ds, g_down_s); cudaGetSymbolAddress(&p_us, g_up_s);

    conv_all<<<(NX4 + 2 * NW4) / 256, 256>>>((const float4*)x, (const float4*)Wd, (const float4*)Wu);
    gate_partial<<<dim3(T_TOK / 32, 2), 256>>>(x, Wg);
    build_lists<<<E_NUM, 256>>>();

    // down: A = split(x) gathered [T,2048], B = split(Wd) [E][256][2048]
    moe_gemm_mma<64><<<dim3(T_TOK / BM, DG / 64, E_NUM), 256, SMEM64>>>(
        (const uint16_t*)p_xh, (const uint16_t*)p_xl, D_DIM,
        (const uint16_t*)p_wdh, (const uint16_t*)p_wdl, D_DIM, DG, (float*)p_ds);
    combine_down_split<<<(T_TOK * DG / 4) / 256, 256>>>();

    // up: A = split(down) gathered [T,256], B = split(Wu) [E][2048][256]
    moe_gemm_mma<64><<<dim3(T_TOK / BM, D_DIM / 64, E_NUM), 256, SMEM64>>>(
        (const uint16_t*)p_dnh, (const uint16_t*)p_dnl, DG,
        (const uint16_t*)p_wuh, (const uint16_t*)p_wul, DG, D_DIM, (float*)p_us);
    combine_up<<<(T_TOK * D_DIM / 4) / 256, 256>>>(out);
}